// round 2
// baseline (speedup 1.0000x reference)
#include <cuda_runtime.h>
#include <math.h>

#define NDIM 64
#define MDIM 32
#define DEG  16     // Chebyshev degree for matrix log on [0.9, 7.0]
#define NT   10     // Taylor degree for matrix exp (spectrum radius ~0.49 after shift)
#define THREADS 256

struct Coefs {
    float cm[DEG + 1];  // cm[1..DEG] Chebyshev coeffs of log
    float c0;           // constant term
    float cc;           // interval center
    float invh;         // 1 / half-width
    float shift;        // exp shift s
    float eshift;       // exp(s)
};

__global__ __launch_bounds__(THREADS, 4)
void spd_pool_kernel(const float* __restrict__ X, float* __restrict__ out, Coefs cf)
{
    __shared__ __align__(16) float sB[NDIM * NDIM];
    __shared__ __align__(16) float sP[NDIM * NDIM];
    __shared__ __align__(16) float sQ[NDIM * NDIM];

    const int tid = threadIdx.x;
    const float* Xb = X + (size_t)blockIdx.x * (NDIM * NDIM);

    // Load X; B = (X - cc*I)/h ; Clenshaw init: U1 = c_D * I, U2 = 0
    for (int e = tid; e < NDIM * NDIM; e += THREADS) {
        int r = e >> 6, c = e & 63;
        float d = (r == c) ? 1.0f : 0.0f;
        sB[e] = (Xb[e] - cf.cc * d) * cf.invh;
        sP[e] = cf.cm[DEG] * d;
        sQ[e] = 0.0f;
    }
    __syncthreads();

    float* U1 = sP;
    float* U2 = sQ;

    // 16x16 thread grid, each thread owns a 4x4 output tile
    const int r0 = (tid >> 4) * 4;
    const int c0 = (tid & 15) * 4;

    // Clenshaw: for k = D-1..1:  Unew = c_k I + 2 B U1 - U2
    //           k = 0 (final):  L    = c_0 I +   B U1 - U2
    for (int k = DEG - 1; k >= 0; k--) {
        const float scale = (k == 0) ? 1.0f : 2.0f;
        const float dcoef = (k == 0) ? cf.c0 : cf.cm[k];

        float acc[4][4];
        #pragma unroll
        for (int i = 0; i < 4; i++)
            #pragma unroll
            for (int j = 0; j < 4; j++) acc[i][j] = 0.0f;

        #pragma unroll 8
        for (int kk = 0; kk < NDIM; kk++) {
            // B symmetric: B[r0+i][kk] == B[kk][r0+i] -> contiguous float4
            float4 av = *(const float4*)&sB[kk * NDIM + r0];
            float4 bv = *(const float4*)&U1[kk * NDIM + c0];
            acc[0][0] += av.x * bv.x; acc[0][1] += av.x * bv.y;
            acc[0][2] += av.x * bv.z; acc[0][3] += av.x * bv.w;
            acc[1][0] += av.y * bv.x; acc[1][1] += av.y * bv.y;
            acc[1][2] += av.y * bv.z; acc[1][3] += av.y * bv.w;
            acc[2][0] += av.z * bv.x; acc[2][1] += av.z * bv.y;
            acc[2][2] += av.z * bv.z; acc[2][3] += av.z * bv.w;
            acc[3][0] += av.w * bv.x; acc[3][1] += av.w * bv.y;
            acc[3][2] += av.w * bv.z; acc[3][3] += av.w * bv.w;
        }

        #pragma unroll
        for (int i = 0; i < 4; i++) {
            int row = r0 + i;
            float4 old = *(const float4*)&U2[row * NDIM + c0];
            float4 nv;
            nv.x = scale * acc[i][0] - old.x;
            nv.y = scale * acc[i][1] - old.y;
            nv.z = scale * acc[i][2] - old.z;
            nv.w = scale * acc[i][3] - old.w;
            int j = row - c0;
            if (j == 0) nv.x += dcoef;
            else if (j == 1) nv.y += dcoef;
            else if (j == 2) nv.z += dcoef;
            else if (j == 3) nv.w += dcoef;
            *(float4*)&U2[row * NDIM + c0] = nv;
        }
        float* t = U1; U1 = U2; U2 = t;
        __syncthreads();
    }
    // U1 now holds L = logm(X)

    // 2x2 average pool -> sB[0..1023] (B no longer needed)
    for (int e = tid; e < MDIM * MDIM; e += THREADS) {
        int r = e >> 5, c = e & 31;
        const float* Lp = U1 + (2 * r) * NDIM + 2 * c;
        sB[e] = 0.25f * (Lp[0] + Lp[1] + Lp[NDIM] + Lp[NDIM + 1]);
    }
    __syncthreads();

    // symmetrize + spectral shift  -> Mm = sB + 1024
    float* Mm = sB + 1024;
    for (int e = tid; e < MDIM * MDIM; e += THREADS) {
        int r = e >> 5, c = e & 31;
        float v = 0.5f * (sB[r * 32 + c] + sB[c * 32 + r]);
        if (r == c) v -= cf.shift;
        Mm[e] = v;
    }
    __syncthreads();

    // expm via Horner Taylor: R = I + M/NT; R = I + (M R)/k, k = NT-1..1
    float* R1 = U2;          // free 4096-float buffer, use two 1024 halves
    float* R2 = U2 + 1024;
    for (int e = tid; e < MDIM * MDIM; e += THREADS) {
        int r = e >> 5, c = e & 31;
        R1[e] = ((r == c) ? 1.0f : 0.0f) + Mm[e] * (1.0f / (float)NT);
    }
    __syncthreads();

    const int er = tid >> 3;          // 0..31
    const int ec = (tid & 7) * 4;     // 0,4,...,28
    for (int k = NT - 1; k >= 1; k--) {
        float invk = 1.0f / (float)k;
        float a0 = 0.f, a1 = 0.f, a2 = 0.f, a3 = 0.f;
        #pragma unroll 8
        for (int kk = 0; kk < MDIM; kk++) {
            float a = Mm[er * 32 + kk];
            float4 bv = *(const float4*)&R1[kk * 32 + ec];
            a0 += a * bv.x; a1 += a * bv.y; a2 += a * bv.z; a3 += a * bv.w;
        }
        float4 nv;
        nv.x = a0 * invk; nv.y = a1 * invk; nv.z = a2 * invk; nv.w = a3 * invk;
        int j = er - ec;
        if (j == 0) nv.x += 1.0f;
        else if (j == 1) nv.y += 1.0f;
        else if (j == 2) nv.z += 1.0f;
        else if (j == 3) nv.w += 1.0f;
        *(float4*)&R2[er * 32 + ec] = nv;
        float* t = R1; R1 = R2; R2 = t;
        __syncthreads();
    }

    // out = exp(shift) * R1   (coalesced float4 store)
    float4* ob = (float4*)(out + (size_t)blockIdx.x * (MDIM * MDIM));
    float4 v = ((const float4*)R1)[tid];
    v.x *= cf.eshift; v.y *= cf.eshift; v.z *= cf.eshift; v.w *= cf.eshift;
    ob[tid] = v;
}

extern "C" void kernel_launch(void* const* d_in, const int* in_sizes, int n_in,
                              void* d_out, int out_size)
{
    const float* X = (const float*)d_in[0];
    float* out = (float*)d_out;
    const int batch = in_sizes[0] / (NDIM * NDIM);

    // Closed-form Chebyshev coefficients of log on [lo, hi]:
    // ln(c + h t) = ln c - ln(1+z^2) - 2 * sum_{k>=1} (z^k / k) T_k(t),
    // z = (sqrt(1-a^2) - 1)/a,  a = h/c.
    const double lo = 0.9, hi = 7.0;
    const double c = 0.5 * (lo + hi);
    const double h = 0.5 * (hi - lo);
    const double al = h / c;
    const double sq = sqrt(1.0 - al * al);
    const double z = (sq - 1.0) / al;   // negative, |z| < 1

    Coefs cf;
    cf.c0 = (float)(log(c) - log(1.0 + z * z));
    cf.cm[0] = 0.0f;
    double zk = 1.0;
    for (int k = 1; k <= DEG; k++) { zk *= z; cf.cm[k] = (float)(-2.0 * zk / k); }
    cf.cc = (float)c;
    cf.invh = (float)(1.0 / h);
    cf.shift = 0.49f;               // pooled spectrum in [0, ~0.97]
    cf.eshift = expf(0.49f);

    spd_pool_kernel<<<batch, THREADS>>>(X, out, cf);
}

// round 3
// speedup vs baseline: 2.7465x; 2.7465x over previous
#include <cuda_runtime.h>
#include <math.h>

#define NDIM 64
#define MDIM 32
#define DEG  11
#define THREADS 256
#define SMEM_BYTES (5 * NDIM * NDIM * (int)sizeof(float))

struct Coefs {
    float a[DEG + 1];   // monomial coeffs of log approx in t, B = (X - cc I)*invh
    float cc, invh;
    float shift, eshift;
};

// C = A * Bop (+ optional epilogue e0*I + e1*Bm + e2*B2m).
// All A operands are symmetric (polynomials of B), so A[row][kk] == A[kk][row],
// letting us load the A-column contiguously as float4.
template <bool EPI>
__device__ __forceinline__ void gemm64(
    const float* __restrict__ A, const float* __restrict__ Bop, float* __restrict__ C,
    const float* __restrict__ Bm, const float* __restrict__ B2m,
    float e0, float e1, float e2, int r0, int c0)
{
    float acc[4][4];
#pragma unroll
    for (int i = 0; i < 4; i++)
#pragma unroll
        for (int j = 0; j < 4; j++) acc[i][j] = 0.0f;

#pragma unroll 8
    for (int kk = 0; kk < NDIM; kk++) {
        float4 av = *(const float4*)&A[kk * NDIM + r0];
        float4 bv = *(const float4*)&Bop[kk * NDIM + c0];
        acc[0][0] += av.x * bv.x; acc[0][1] += av.x * bv.y;
        acc[0][2] += av.x * bv.z; acc[0][3] += av.x * bv.w;
        acc[1][0] += av.y * bv.x; acc[1][1] += av.y * bv.y;
        acc[1][2] += av.y * bv.z; acc[1][3] += av.y * bv.w;
        acc[2][0] += av.z * bv.x; acc[2][1] += av.z * bv.y;
        acc[2][2] += av.z * bv.z; acc[2][3] += av.z * bv.w;
        acc[3][0] += av.w * bv.x; acc[3][1] += av.w * bv.y;
        acc[3][2] += av.w * bv.z; acc[3][3] += av.w * bv.w;
    }

#pragma unroll
    for (int i = 0; i < 4; i++) {
        int row = r0 + i;
        float4 nv = make_float4(acc[i][0], acc[i][1], acc[i][2], acc[i][3]);
        if (EPI) {
            float4 b  = *(const float4*)&Bm[row * NDIM + c0];
            float4 b2 = *(const float4*)&B2m[row * NDIM + c0];
            nv.x += e1 * b.x + e2 * b2.x;
            nv.y += e1 * b.y + e2 * b2.y;
            nv.z += e1 * b.z + e2 * b2.z;
            nv.w += e1 * b.w + e2 * b2.w;
            int j = row - c0;
            if (j == 0) nv.x += e0;
            else if (j == 1) nv.y += e0;
            else if (j == 2) nv.z += e0;
            else if (j == 3) nv.w += e0;
        }
        *(float4*)&C[row * NDIM + c0] = nv;
    }
}

// 32x32 GEMM, 16x16 thread grid, 2x2 tiles. C = A * Bop.
__device__ __forceinline__ void gemm32(
    const float* __restrict__ A, const float* __restrict__ Bop, float* __restrict__ C,
    int r0, int c0)
{
    float a00 = 0.f, a01 = 0.f, a10 = 0.f, a11 = 0.f;
#pragma unroll 8
    for (int kk = 0; kk < MDIM; kk++) {
        float2 av = *(const float2*)&A[kk * MDIM + r0];
        float2 bv = *(const float2*)&Bop[kk * MDIM + c0];
        a00 += av.x * bv.x; a01 += av.x * bv.y;
        a10 += av.y * bv.x; a11 += av.y * bv.y;
    }
    *(float2*)&C[r0 * MDIM + c0] = make_float2(a00, a01);
    *(float2*)&C[(r0 + 1) * MDIM + c0] = make_float2(a10, a11);
}

__global__ __launch_bounds__(THREADS, 2)
void spd_pool_kernel(const float* __restrict__ X, float* __restrict__ out, Coefs cf)
{
    extern __shared__ float sm[];
    float* sB  = sm;
    float* sB2 = sm + 4096;
    float* sB3 = sm + 8192;
    float* sT  = sm + 12288;
    float* sU  = sm + 16384;

    const int tid = threadIdx.x;
    const float* Xb = X + (size_t)blockIdx.x * (NDIM * NDIM);

    // B = (X - cc*I) * invh   (spectrum of B in [-1, 1])
    for (int e = tid; e < NDIM * NDIM; e += THREADS) {
        int r = e >> 6, c = e & 63;
        float d = (r == c) ? cf.cc : 0.0f;
        sB[e] = (Xb[e] - d) * cf.invh;
    }
    __syncthreads();

    const int r0 = (tid >> 4) * 4;
    const int c0 = (tid & 15) * 4;

    // Powers
    gemm64<false>(sB,  sB, sB2, sB, sB2, 0.f, 0.f, 0.f, r0, c0);
    __syncthreads();
    gemm64<false>(sB2, sB, sB3, sB, sB2, 0.f, 0.f, 0.f, r0, c0);
    __syncthreads();

    // G3 = a9 I + a10 B + a11 B2
    for (int e = tid; e < NDIM * NDIM; e += THREADS) {
        int r = e >> 6, c = e & 63;
        sT[e] = cf.a[10] * sB[e] + cf.a[11] * sB2[e] + ((r == c) ? cf.a[9] : 0.0f);
    }
    __syncthreads();

    // Horner in B3 with fused group epilogues
    gemm64<true>(sT, sB3, sU, sB, sB2, cf.a[6], cf.a[7], cf.a[8], r0, c0);
    __syncthreads();
    gemm64<true>(sU, sB3, sT, sB, sB2, cf.a[3], cf.a[4], cf.a[5], r0, c0);
    __syncthreads();
    gemm64<true>(sT, sB3, sU, sB, sB2, cf.a[0], cf.a[1], cf.a[2], r0, c0);
    __syncthreads();
    // L = logm(X) now in sU

    // 2x2 average pool + spectral shift; 32x32 workspaces live inside sB
    float* sM  = sB;
    float* sM2 = sB + 1024;
    float* sM3 = sB + 2048;
    float* sT2 = sB + 3072;
    for (int e = tid; e < MDIM * MDIM; e += THREADS) {
        int r = e >> 5, c = e & 31;
        const float* Lp = sU + (2 * r) * NDIM + 2 * c;
        float v = 0.25f * (Lp[0] + Lp[1] + Lp[NDIM] + Lp[NDIM + 1]);
        if (r == c) v -= cf.shift;
        sM[e] = v;
    }
    __syncthreads();

    // expm via degree-6 Taylor, Paterson-Stockmeyer (s=3)
    const float b0 = 1.0f, b1 = 1.0f, b2 = 0.5f;
    const float b3 = 1.0f / 6.0f, b4 = 1.0f / 24.0f, b5 = 1.0f / 120.0f, b6 = 1.0f / 720.0f;

    const int er0 = (tid >> 4) * 2;
    const int ec0 = (tid & 15) * 2;

    gemm32(sM,  sM, sM2, er0, ec0);
    __syncthreads();
    gemm32(sM2, sM, sM3, er0, ec0);
    __syncthreads();

    // T2 = b6 M3 + b5 M2 + b4 M + b3 I
    for (int e = tid; e < MDIM * MDIM; e += THREADS) {
        int r = e >> 5, c = e & 31;
        sT2[e] = b6 * sM3[e] + b5 * sM2[e] + b4 * sM[e] + ((r == c) ? b3 : 0.0f);
    }
    __syncthreads();

    // R = T2*M3 + b2 M2 + b1 M + b0 I, scaled by e^shift, streamed to global
    {
        float a00 = 0.f, a01 = 0.f, a10 = 0.f, a11 = 0.f;
#pragma unroll 8
        for (int kk = 0; kk < MDIM; kk++) {
            float2 av = *(const float2*)&sT2[kk * MDIM + er0];
            float2 bv = *(const float2*)&sM3[kk * MDIM + ec0];
            a00 += av.x * bv.x; a01 += av.x * bv.y;
            a10 += av.y * bv.x; a11 += av.y * bv.y;
        }
        float* ob = out + (size_t)blockIdx.x * (MDIM * MDIM);
#pragma unroll
        for (int i = 0; i < 2; i++) {
            int row = er0 + i;
            float2 m  = *(const float2*)&sM [row * MDIM + ec0];
            float2 m2 = *(const float2*)&sM2[row * MDIM + ec0];
            float v0 = (i == 0) ? a00 : a10;
            float v1 = (i == 0) ? a01 : a11;
            float2 nv;
            nv.x = v0 + b2 * m2.x + b1 * m.x;
            nv.y = v1 + b2 * m2.y + b1 * m.y;
            int j = row - ec0;
            if (j == 0) nv.x += b0;
            else if (j == 1) nv.y += b0;
            nv.x *= cf.eshift;
            nv.y *= cf.eshift;
            *(float2*)&ob[row * MDIM + ec0] = nv;
        }
    }
}

extern "C" void kernel_launch(void* const* d_in, const int* in_sizes, int n_in,
                              void* d_out, int out_size)
{
    const float* X = (const float*)d_in[0];
    float* out = (float*)d_out;
    const int batch = in_sizes[0] / (NDIM * NDIM);

    // log(c + h t), t in [-1,1], Chebyshev series ln(c+ht) = c0 - 2 sum z^k/k T_k(t),
    // z = (sqrt(1-al^2)-1)/al, al = h/c. Spectrum of X in [1, ~5.8]; use [0.98, 6.3].
    const double lo = 0.98, hi = 6.3;
    const double c = 0.5 * (lo + hi);
    const double h = 0.5 * (hi - lo);
    const double al = h / c;
    const double z = (sqrt(1.0 - al * al) - 1.0) / al;

    // Chebyshev coefficients
    double ck[DEG + 1];
    ck[0] = log(c) - log(1.0 + z * z);
    double zk = 1.0;
    for (int k = 1; k <= DEG; k++) { zk *= z; ck[k] = -2.0 * zk / k; }

    // Convert to monomial basis (double): T_k(t) recurrence
    static double T[DEG + 1][DEG + 1];
    for (int k = 0; k <= DEG; k++)
        for (int j = 0; j <= DEG; j++) T[k][j] = 0.0;
    T[0][0] = 1.0; T[1][1] = 1.0;
    for (int k = 2; k <= DEG; k++)
        for (int j = 0; j <= k; j++)
            T[k][j] = (j > 0 ? 2.0 * T[k - 1][j - 1] : 0.0) - T[k - 2][j];

    double ad[DEG + 1];
    for (int j = 0; j <= DEG; j++) ad[j] = 0.0;
    for (int k = 0; k <= DEG; k++)
        for (int j = 0; j <= k; j++) ad[j] += ck[k] * T[k][j];

    Coefs cf;
    for (int j = 0; j <= DEG; j++) cf.a[j] = (float)ad[j];
    cf.cc = (float)c;
    cf.invh = (float)(1.0 / h);
    cf.shift = 0.46f;                 // pooled spectrum in [0, 0.5*ln(6.3)] ~ [0, 0.92]
    cf.eshift = expf(0.46f);

    cudaFuncSetAttribute(spd_pool_kernel,
                         cudaFuncAttributeMaxDynamicSharedMemorySize, SMEM_BYTES);
    spd_pool_kernel<<<batch, THREADS, SMEM_BYTES>>>(X, out, cf);
}